// round 17
// baseline (speedup 1.0000x reference)
#include <cuda_runtime.h>
#include <cstdint>

// Fixed problem shape: B=4, H=W=256, DIM=192, NH=6, HD=32, WS=8
__device__ float g_qkv[150994944];   // B*65536*576
__device__ float g_o[50331648];      // B*65536*192
__device__ float g_wq[110592];       // qkv_w pre-rounded to tf32
__device__ float g_wo[36864];        // out_w pre-rounded to tf32

// ======================= helpers =======================
__device__ __forceinline__ uint32_t smem_u32(const void* p) {
    uint32_t a;
    asm("{ .reg .u64 t; cvta.to.shared.u64 t, %1; cvt.u32.u64 %0, t; }" : "=r"(a) : "l"(p));
    return a;
}
__device__ __forceinline__ void cp_async16(uint32_t dst, const void* src) {
    asm volatile("cp.async.cg.shared.global [%0], [%1], 16;" :: "r"(dst), "l"(src));
}
#define CP_COMMIT() asm volatile("cp.async.commit_group;" ::: "memory")
#define CP_WAIT1()  asm volatile("cp.async.wait_group 1;" ::: "memory")
#define CP_WAIT0()  asm volatile("cp.async.wait_group 0;" ::: "memory")

__device__ __forceinline__ uint32_t to_tf32(float f) {
    uint32_t r;
    asm("cvt.rna.tf32.f32 %0, %1;" : "=r"(r) : "f"(f));
    return r;
}
__device__ __forceinline__ float rnd(float f) { return __uint_as_float(to_tf32(f)); }

__device__ __forceinline__ void mma_tf32(float* c, const uint32_t* a, uint32_t b0, uint32_t b1) {
    asm volatile(
        "mma.sync.aligned.m16n8k8.row.col.f32.tf32.tf32.f32 "
        "{%0,%1,%2,%3}, {%4,%5,%6,%7}, {%8,%9}, {%0,%1,%2,%3};"
        : "+f"(c[0]), "+f"(c[1]), "+f"(c[2]), "+f"(c[3])
        : "r"(a[0]), "r"(a[1]), "r"(a[2]), "r"(a[3]), "r"(b0), "r"(b1));
}

// ======================= weight pre-round =======================
__global__ void wconv_kernel(const float* __restrict__ w1, float* __restrict__ o1, int n1,
                             const float* __restrict__ w2, float* __restrict__ o2, int n2) {
    int i = blockIdx.x * blockDim.x + threadIdx.x;
    int stride = gridDim.x * blockDim.x;
    for (int j = i; j < n1; j += stride) o1[j] = rnd(w1[j]);
    for (int j = i; j < n2; j += stride) o2[j] = rnd(w2[j]);
}

// ======================= tf32 mma.sync GEMM (128x64 tile, 3 CTAs/SM) =======================
// C[M,N] = A[M,K] @ W[N,K]^T + bias.  W pre-rounded tf32.
// CTA tile 128(M) x 64(N), BK=32, 256 threads = 8 warps (4m x 2n), warp 32x32.
#define APAD 36
static const int GEMM_SMEM = 2 * (128 + 64) * APAD * 4;   // 55296 B dynamic

__global__ __launch_bounds__(256, 3) void gemm_tc(
    const float* __restrict__ A, const float* __restrict__ W,
    const float* __restrict__ bias, float* __restrict__ C,
    int M, int N, int K)
{
    extern __shared__ float smem[];
    float* sAp[2] = { smem,              smem + 192 * APAD };
    float* sBp[2] = { smem + 128 * APAD, smem + 192 * APAD + 128 * APAD };
    const uint32_t aU[2] = { smem_u32(sAp[0]), smem_u32(sAp[1]) };
    const uint32_t bU[2] = { smem_u32(sBp[0]), smem_u32(sBp[1]) };

    const int tid = threadIdx.x;
    const int bm = blockIdx.y * 128;
    const int bn = blockIdx.x * 64;
    const int nch = K / 32;

    const int wid = tid >> 5, lane = tid & 31;
    const int wm = wid & 3;        // m: wm*32 (two m16 tiles)
    const int wn = wid >> 2;       // n: wn*32 (four n8 tiles)
    const int g = lane >> 2, tg = lane & 3;

    float acc[2][4][4];
#pragma unroll
    for (int mt = 0; mt < 2; mt++)
#pragma unroll
        for (int nt = 0; nt < 4; nt++)
#pragma unroll
            for (int j = 0; j < 4; j++) acc[mt][nt][j] = 0.f;

    auto load_tile = [&](int kc, int bsel) {
#pragma unroll
        for (int i = 0; i < 4; i++) {              // A: 1024 float4
            int idx = tid + i * 256;
            int row = idx >> 3, c4 = idx & 7;
            cp_async16(aU[bsel] + (row * APAD + c4 * 4) * 4,
                       &A[(size_t)(bm + row) * K + kc * 32 + c4 * 4]);
        }
#pragma unroll
        for (int i = 0; i < 2; i++) {              // B: 512 float4
            int idx = tid + i * 256;
            int row = idx >> 3, c4 = idx & 7;
            cp_async16(bU[bsel] + (row * APAD + c4 * 4) * 4,
                       &W[(size_t)(bn + row) * K + kc * 32 + c4 * 4]);
        }
    };

    load_tile(0, 0); CP_COMMIT();
    load_tile(1, 1); CP_COMMIT();

    for (int kc = 0; kc < nch; kc++) {
        const int bsel = kc & 1;
        CP_WAIT1();
        __syncthreads();

        const float* As = sAp[bsel];
        const float* Bs = sBp[bsel];
#pragma unroll
        for (int ks = 0; ks < 4; ks++) {
            const int k0 = ks * 8;
            uint32_t a[2][4];
#pragma unroll
            for (int mt = 0; mt < 2; mt++) {
                int rr = wm * 32 + mt * 16 + g;
                a[mt][0] = to_tf32(As[rr * APAD + k0 + tg]);
                a[mt][1] = to_tf32(As[(rr + 8) * APAD + k0 + tg]);
                a[mt][2] = to_tf32(As[rr * APAD + k0 + tg + 4]);
                a[mt][3] = to_tf32(As[(rr + 8) * APAD + k0 + tg + 4]);
            }
#pragma unroll
            for (int nt = 0; nt < 4; nt++) {
                int n0 = wn * 32 + nt * 8 + g;
                uint32_t b0 = __float_as_uint(Bs[n0 * APAD + k0 + tg]);   // pre-tf32
                uint32_t b1 = __float_as_uint(Bs[n0 * APAD + k0 + tg + 4]);
                mma_tf32(acc[0][nt], a[0], b0, b1);
                mma_tf32(acc[1][nt], a[1], b0, b1);
            }
        }
        __syncthreads();
        if (kc + 2 < nch) load_tile(kc + 2, bsel);
        CP_COMMIT();
    }

    // epilogue: bias + store
#pragma unroll
    for (int mt = 0; mt < 2; mt++) {
        const int row0 = bm + wm * 32 + mt * 16 + g;
#pragma unroll
        for (int nt = 0; nt < 4; nt++) {
            int col = bn + wn * 32 + nt * 8 + tg * 2;
            float2 bb = *(const float2*)&bias[col];
            *(float2*)&C[(size_t)row0 * N + col] =
                make_float2(acc[mt][nt][0] + bb.x, acc[mt][nt][1] + bb.y);
            *(float2*)&C[(size_t)(row0 + 8) * N + col] =
                make_float2(acc[mt][nt][2] + bb.x, acc[mt][nt][3] + bb.y);
        }
    }
}

// ======================= tensorized windowed attention + LePE =======================
// one CTA = one (window, head). 128 threads = 4 warps. grid (4096, 6).
// smem 38.0 KB (sP aliases sQ|sK) -> 6 CTAs/SM.
__global__ __launch_bounds__(128) void attn_kernel(
    const float* __restrict__ qkv, const float* __restrict__ pe_w,
    const float* __restrict__ pe_b, float* __restrict__ O)
{
    __shared__ float sQKP[4608];     // q[0..2303] | k[2304..4607]; sP[0..4351] aliases after logits
    __shared__ float sVr[2304];      // raw v staging (64x36)
    __shared__ float sVt[2176];      // v transposed [d][s] (32x68), tf32-rounded
    __shared__ float sPE[384];
    __shared__ float sPEb[32];

    float* sQ = sQKP;
    float* sK = sQKP + 2304;
    float* sP = sQKP;                // alias: written only after all sQ/sK reads complete
    const uint32_t uQ = smem_u32(sQ), uK = smem_u32(sK), uVr = smem_u32(sVr);

    const int w = blockIdx.x;
    const int h = blockIdx.y;
    const int bb = w >> 10;
    const int wy = (w & 1023) >> 5, wx = w & 31;
    const int tid = threadIdx.x;
    const int wid = tid >> 5, lane = tid & 31;
    const int g = lane >> 2, tg = lane & 3;

    // ---- gather q,k,v via cp.async (one 128B line per (token,tensor)) ----
#pragma unroll
    for (int i = 0; i < 12; i++) {
        int idx = tid + i * 128;        // 1536 float4
        int t = idx / 24, j = idx % 24;
        int which = j >> 3, c4 = j & 7;
        int n = (wy * 8 + (t >> 3)) * 256 + wx * 8 + (t & 7);
        const float* src = &qkv[((size_t)(bb * 65536 + n)) * 576 + h * 32 + which * 192 + c4 * 4];
        uint32_t dst = (which == 0 ? uQ : which == 1 ? uK : uVr) + (t * 36 + c4 * 4) * 4;
        cp_async16(dst, src);
    }
    CP_COMMIT();
    // pe weights
    for (int i = tid; i < 288; i += 128)
        sPE[(i / 9) * 12 + i % 9] = pe_w[h * 288 + i];
    if (tid < 32) sPEb[tid] = pe_b[h * 32 + tid];
    CP_WAIT0();
    __syncthreads();

    // ---- transpose v -> sVt[d][s], rounded ----
#pragma unroll
    for (int i = 0; i < 16; i++) {
        int idx = tid + i * 128;
        int s = idx >> 5, d = idx & 31;
        sVt[d * 68 + s] = rnd(sVr[s * 36 + d]);
    }
    __syncthreads();

    // ---- logits(64x64) = q @ k^T (accumulate fully in regs BEFORE writing sP) ----
    const int r0 = wid * 16 + g;
    float bacc[8][4];
#pragma unroll
    for (int nt = 0; nt < 8; nt++)
#pragma unroll
        for (int j = 0; j < 4; j++) bacc[nt][j] = 0.f;
#pragma unroll
    for (int ks = 0; ks < 4; ks++) {
        const int k0 = ks * 8;
        uint32_t a[4];
        a[0] = to_tf32(sQ[r0 * 36 + k0 + tg]);
        a[1] = to_tf32(sQ[(r0 + 8) * 36 + k0 + tg]);
        a[2] = to_tf32(sQ[r0 * 36 + k0 + tg + 4]);
        a[3] = to_tf32(sQ[(r0 + 8) * 36 + k0 + tg + 4]);
#pragma unroll
        for (int nt = 0; nt < 8; nt++) {
            int n0 = nt * 8 + g;
            uint32_t b0 = to_tf32(sK[n0 * 36 + k0 + tg]);
            uint32_t b1 = to_tf32(sK[n0 * 36 + k0 + tg + 4]);
            mma_tf32(bacc[nt], a, b0, b1);
        }
    }
    __syncthreads();   // all sQ/sK reads done -> safe to overwrite via sP alias

    {
        const float scale = 0.17677669529663687f;
#pragma unroll
        for (int nt = 0; nt < 8; nt++) {
            int s = nt * 8 + tg * 2;
            sP[r0 * 68 + s]       = bacc[nt][0] * scale;
            sP[r0 * 68 + s + 1]   = bacc[nt][1] * scale;
            sP[(r0 + 8) * 68 + s]     = bacc[nt][2] * scale;
            sP[(r0 + 8) * 68 + s + 1] = bacc[nt][3] * scale;
        }
    }
    __syncthreads();

    // ---- softmax: 2 threads per row, 32 cols each; write rounded probs ----
    {
        int t = tid >> 1, q = tid & 1;
        float* row = sP + t * 68 + q * 32;
        float v[32];
#pragma unroll
        for (int j = 0; j < 8; j++) *(float4*)&v[j * 4] = *(float4*)&row[j * 4];
        float m = v[0];
#pragma unroll
        for (int j = 1; j < 32; j++) m = fmaxf(m, v[j]);
        m = fmaxf(m, __shfl_xor_sync(0xffffffffu, m, 1));
        float s = 0.f;
#pragma unroll
        for (int j = 0; j < 32; j++) { v[j] = __expf(v[j] - m); s += v[j]; }
        s += __shfl_xor_sync(0xffffffffu, s, 1);
        float inv = 1.0f / s;
#pragma unroll
        for (int j = 0; j < 32; j++) v[j] = rnd(v[j] * inv);
#pragma unroll
        for (int j = 0; j < 8; j++) *(float4*)&row[j * 4] = *(float4*)&v[j * 4];
    }
    __syncthreads();

    // ---- PV: o(64x32) = P @ v  (operands pre-rounded), + LePE, store ----
    {
        float dacc[4][4];
#pragma unroll
        for (int nt = 0; nt < 4; nt++)
#pragma unroll
            for (int j = 0; j < 4; j++) dacc[nt][j] = 0.f;
#pragma unroll
        for (int ks = 0; ks < 8; ks++) {
            const int k0 = ks * 8;
            uint32_t a[4];
            a[0] = __float_as_uint(sP[r0 * 68 + k0 + tg]);
            a[1] = __float_as_uint(sP[(r0 + 8) * 68 + k0 + tg]);
            a[2] = __float_as_uint(sP[r0 * 68 + k0 + tg + 4]);
            a[3] = __float_as_uint(sP[(r0 + 8) * 68 + k0 + tg + 4]);
#pragma unroll
            for (int nt = 0; nt < 4; nt++) {
                int n0 = nt * 8 + g;
                uint32_t b0 = __float_as_uint(sVt[n0 * 68 + k0 + tg]);
                uint32_t b1 = __float_as_uint(sVt[n0 * 68 + k0 + tg + 4]);
                mma_tf32(dacc[nt], a, b0, b1);
            }
        }
        // LePE + store
#pragma unroll
        for (int nt = 0; nt < 4; nt++) {
            const int d0 = nt * 8 + tg * 2;
            float pb0 = sPEb[d0], pb1 = sPEb[d0 + 1];
#pragma unroll
            for (int i = 0; i < 2; i++) {
                int t = r0 + i * 8;
                int ty = t >> 3, tx = t & 7;
                float l0 = pb0, l1 = pb1;
#pragma unroll
                for (int ky = 0; ky < 3; ky++) {
                    int yy = ty + ky - 1;
                    if (yy < 0 || yy > 7) continue;
#pragma unroll
                    for (int kx = 0; kx < 3; kx++) {
                        int xx = tx + kx - 1;
                        if (xx < 0 || xx > 7) continue;
                        int ss = yy * 8 + xx;
                        l0 += sPE[d0 * 12 + ky * 3 + kx] * sVt[d0 * 68 + ss];
                        l1 += sPE[(d0 + 1) * 12 + ky * 3 + kx] * sVt[(d0 + 1) * 68 + ss];
                    }
                }
                int n = (wy * 8 + ty) * 256 + wx * 8 + tx;
                size_t base = ((size_t)(bb * 65536 + n)) * 192 + h * 32 + d0;
                *(float2*)&O[base] = make_float2(dacc[nt][2 * i] + l0, dacc[nt][2 * i + 1] + l1);
            }
        }
    }
}

// ======================= launcher =======================
extern "C" void kernel_launch(void* const* d_in, const int* in_sizes, int n_in,
                              void* d_out, int out_size) {
    const float* x     = (const float*)d_in[0];
    const float* qkv_w = (const float*)d_in[1];
    const float* qkv_b = (const float*)d_in[2];
    const float* pe_w  = (const float*)d_in[3];
    const float* pe_b  = (const float*)d_in[4];
    const float* out_w = (const float*)d_in[5];
    const float* out_b = (const float*)d_in[6];
    float* out = (float*)d_out;

    const int B = in_sizes[0] / (65536 * 192);
    const int M = B * 65536;

    int dev = 0;
    cudaGetDevice(&dev);   // harmless context touch

    float *qkv_s, *o_s, *wq_s, *wo_s;
    cudaGetSymbolAddress((void**)&qkv_s, g_qkv);
    cudaGetSymbolAddress((void**)&o_s, g_o);
    cudaGetSymbolAddress((void**)&wq_s, g_wq);
    cudaGetSymbolAddress((void**)&wo_s, g_wo);

    static bool attr_set = false;
    if (!attr_set) {
        cudaFuncSetAttribute(gemm_tc, cudaFuncAttributeMaxDynamicSharedMemorySize, GEMM_SMEM);
        attr_set = true;
    }

    wconv_kernel<<<144, 256>>>(qkv_w, wq_s, 110592, out_w, wo_s, 36864);

    dim3 g1(9, M / 128);
    gemm_tc<<<g1, 256, GEMM_SMEM>>>(x, wq_s, qkv_b, qkv_s, M, 576, 192);

    dim3 g2(B * 1024, 6);
    attn_kernel<<<g2, 128>>>(qkv_s, pe_w, pe_b, o_s);

    dim3 g3(3, M / 128);
    gemm_tc<<<g3, 256, GEMM_SMEM>>>(o_s, wo_s, out_b, out, M, 192, 192);
}